// round 16
// baseline (speedup 1.0000x reference)
#include <cuda_runtime.h>
#include <cstdint>

// ---------------------------------------------------------------------------
// SABlock: causal MHA block. B=4, T=2048, C=1024, H=16, D=64.
// Round 16: round-15 retry with GEMM smem made DYNAMIC (3-stage = 60KB >
// 48KB static limit). (a) log2e folded into Wq; (b) raw-fp32 P into MMA;
// (c) 3-stage cp.async GEMM pipeline (wait_group 1).
// ---------------------------------------------------------------------------

#define BB 4
#define TT 2048
#define CC 1024
#define HH 16
#define DD 64

__device__ __align__(16) float g_X[BB * TT * CC];
__device__ __align__(16) float g_Wq[CC * CC];
__device__ __align__(16) float g_Wk[CC * CC];
__device__ __align__(16) float g_Wv[CC * CC];
__device__ __align__(16) float g_Wo[CC * CC];
__device__ __align__(16) float g_Q[BB * HH * TT * DD];
__device__ __align__(16) float g_K[BB * HH * TT * DD];
__device__ __align__(16) float g_V[BB * HH * TT * DD];
__device__ __align__(16) float g_Y[BB * TT * CC];

__device__ __forceinline__ float to_tf32(float x) {
    uint32_t u;
    asm("cvt.rna.tf32.f32 %0, %1;" : "=r"(u) : "f"(x));
    return __uint_as_float(u);
}
__device__ __forceinline__ uint32_t smem_u32(const void* p) {
    return (uint32_t)__cvta_generic_to_shared(p);
}

#define CPA16(dst, src)                                                       \
    asm volatile("cp.async.cg.shared.global [%0], [%1], 16;"                  \
                 :: "r"(dst), "l"(src) : "memory")
#define CPA_COMMIT() asm volatile("cp.async.commit_group;" ::: "memory")
#define CPA_WAIT0()  asm volatile("cp.async.wait_group 0;" ::: "memory")
#define CPA_WAIT1()  asm volatile("cp.async.wait_group 1;" ::: "memory")

#define LDSM4(r, addr)                                                        \
    asm volatile("ldmatrix.sync.aligned.m8n8.x4.shared.b16 {%0,%1,%2,%3}, [%4];" \
                 : "=r"((r)[0]), "=r"((r)[1]), "=r"((r)[2]), "=r"((r)[3])     \
                 : "r"(addr))

#define MMA_TF32(c, a, b0_, b1_)                                              \
    asm volatile("mma.sync.aligned.m16n8k8.row.col.f32.tf32.tf32.f32 "        \
                 "{%0,%1,%2,%3},{%4,%5,%6,%7},{%8,%9},{%0,%1,%2,%3};"         \
                 : "+f"((c)[0]), "+f"((c)[1]), "+f"((c)[2]), "+f"((c)[3])     \
                 : "r"((a)[0]), "r"((a)[1]), "r"((a)[2]), "r"((a)[3]),        \
                   "r"(b0_), "r"(b1_))

// A-frag direct from S accumulator: register order (c0, c2, c1, c3).
#define MMA_TF32_ACC_A(c, s0_, s1_, s2_, s3_, b0_, b1_)                       \
    asm volatile("mma.sync.aligned.m16n8k8.row.col.f32.tf32.tf32.f32 "        \
                 "{%0,%1,%2,%3},{%4,%5,%6,%7},{%8,%9},{%0,%1,%2,%3};"         \
                 : "+f"((c)[0]), "+f"((c)[1]), "+f"((c)[2]), "+f"((c)[3])     \
                 : "r"(s0_), "r"(s2_), "r"(s1_), "r"(s3_),                    \
                   "r"(b0_), "r"(b1_))

// ---------------------------------------------------------------------------
// Kernel 0a: RNA-round x -> g_X. Kernel 0b: round weights.
// Wq pre-scaled by 0.125*log2(e) -> QK^T lands directly in log2 domain.
// ---------------------------------------------------------------------------
__global__ void round_x_kernel(const float* __restrict__ src, int n4)
{
    int i = blockIdx.x * blockDim.x + threadIdx.x;
    if (i < n4) {
        float4 v = ((const float4*)src)[i];
        ((float4*)g_X)[i] = make_float4(to_tf32(v.x), to_tf32(v.y),
                                        to_tf32(v.z), to_tf32(v.w));
    }
}

__global__ void round_w_kernel(const float* __restrict__ wq,
                               const float* __restrict__ wk,
                               const float* __restrict__ wv,
                               const float* __restrict__ wo, int n4)
{
    const int y = blockIdx.y;
    const float* src = (y == 0) ? wq : (y == 1) ? wk : (y == 2) ? wv : wo;
    float* dst = (y == 0) ? g_Wq : (y == 1) ? g_Wk : (y == 2) ? g_Wv : g_Wo;
    const float sc = (y == 0) ? 0.125f * 1.4426950408889634f : 1.0f;
    int i = blockIdx.x * blockDim.x + threadIdx.x;
    if (i < n4) {
        float4 v = ((const float4*)src)[i];
        ((float4*)dst)[i] = make_float4(to_tf32(v.x * sc), to_tf32(v.y * sc),
                                        to_tf32(v.z * sc), to_tf32(v.w * sc));
    }
}

// ---------------------------------------------------------------------------
// tf32 GEMM core, 3-stage cp.async pipeline, DYNAMIC smem (60KB).
// Layout: As[3][128][20] then Bs[3][128][20]. 4 warps 64x64, K-step 16.
// ---------------------------------------------------------------------------
#define KT_STEPS (CC / 16)               // 64
#define GSTAGE   (128 * 20)              // floats per stage per array
#define GEMM_SMEM_BYTES (6 * GSTAGE * 4) // 61440

__device__ __forceinline__ void gemm_tf32(float* smbase,
                                          const float* __restrict__ A,
                                          const float* __restrict__ W,
                                          int m0, int n0, float acc[4][8][4])
{
    float* As = smbase;                 // [3][128][20]
    float* Bs = smbase + 3 * GSTAGE;    // [3][128][20]

    const int t    = threadIdx.x;
    const int lane = t & 31;
    const int wid  = t >> 5;
    const int wm   = (wid & 1) * 64;
    const int wn   = (wid >> 1) * 64;

    const int lr = t >> 2;                  // 0..31
    const int lc = (t & 3) * 4;             // 0,4,8,12
    const float* Ap = A + (size_t)(m0 + lr) * CC + lc;
    const float* Bp = W + (size_t)(n0 + lr) * CC + lc;

    const uint32_t aSt = smem_u32(As) + lr * 80 + lc * 4;
    const uint32_t bSt = smem_u32(Bs) + lr * 80 + lc * 4;

    const int arow = (lane & 7) + ((lane >> 3) & 1) * 8;
    const int akw  = (lane >> 4) * 4;
    const int brow = (lane & 7) + (lane >> 4) * 8;
    const int bkw  = ((lane >> 3) & 1) * 4;

    const uint32_t aBase = smem_u32(As) + (((wm + arow) * 20 + akw) << 2);
    const uint32_t bBase = smem_u32(Bs) + (((wn + brow) * 20 + bkw) << 2);
    const uint32_t BUF   = GSTAGE * 4;      // 10240 bytes per stage

    #pragma unroll
    for (int i = 0; i < 4; i++)
        #pragma unroll
        for (int nt = 0; nt < 8; nt++)
            #pragma unroll
            for (int c = 0; c < 4; c++) acc[i][nt][c] = 0.f;

    // prologue: stages 0 and 1
    #pragma unroll
    for (int s = 0; s < 2; s++) {
        #pragma unroll
        for (int i = 0; i < 4; i++) {
            CPA16(aSt + s * BUF + i * 2560, Ap + s * 16 + (size_t)(32 * i) * CC);
            CPA16(bSt + s * BUF + i * 2560, Bp + s * 16 + (size_t)(32 * i) * CC);
        }
        CPA_COMMIT();
    }

    int cur = 0;
    for (int kt = 0; kt < KT_STEPS; kt++) {
        if (kt == KT_STEPS - 1) { CPA_WAIT0(); } else { CPA_WAIT1(); }
        __syncthreads();

        if (kt + 2 < KT_STEPS) {
            int nb = cur + 2; if (nb >= 3) nb -= 3;
            const float* Ap2 = Ap + (kt + 2) * 16;
            const float* Bp2 = Bp + (kt + 2) * 16;
            #pragma unroll
            for (int i = 0; i < 4; i++) {
                CPA16(aSt + nb * BUF + i * 2560, Ap2 + (size_t)(32 * i) * CC);
                CPA16(bSt + nb * BUF + i * 2560, Bp2 + (size_t)(32 * i) * CC);
            }
            CPA_COMMIT();
        }

        const uint32_t aB = aBase + cur * BUF;
        const uint32_t bB = bBase + cur * BUF;
        #pragma unroll
        for (int kk = 0; kk < 2; kk++) {
            uint32_t a[4][4];
            #pragma unroll
            for (int i = 0; i < 4; i++)
                LDSM4(a[i], aB + i * 1280 + kk * 32);
            #pragma unroll
            for (int p = 0; p < 4; p++) {
                uint32_t b[4];
                LDSM4(b, bB + p * 1280 + kk * 32);
                #pragma unroll
                for (int i = 0; i < 4; i++) {
                    MMA_TF32(acc[i][2 * p],     a[i], b[0], b[1]);
                    MMA_TF32(acc[i][2 * p + 1], a[i], b[2], b[3]);
                }
            }
        }
        if (++cur == 3) cur = 0;
    }
}

// ---------------------------------------------------------------------------
// Kernel 1: fused QKV projection. grid = (8, 64, 3), 128 threads, dyn smem.
// ---------------------------------------------------------------------------
__global__ void __launch_bounds__(128) qkv_kernel()
{
    extern __shared__ float gsm[];
    const int z = blockIdx.z;
    const float* W = (z == 0) ? g_Wq : (z == 1) ? g_Wk : g_Wv;
    float* dst     = (z == 0) ? g_Q : (z == 1) ? g_K : g_V;

    const int m0 = blockIdx.y * 128;
    const int n0 = blockIdx.x * 128;

    float acc[4][8][4];
    gemm_tf32(gsm, g_X, W, m0, n0, acc);

    const int lane = threadIdx.x & 31, wid = threadIdx.x >> 5;
    const int g = lane >> 2, ctid = lane & 3;
    const int wm = (wid & 1) * 64, wn = (wid >> 1) * 64;

    #pragma unroll
    for (int i = 0; i < 4; i++) {
        const int m = m0 + wm + 16 * i + g;
        const int b1 = m >> 11;
        const int t1 = m & (TT - 1);
        #pragma unroll
        for (int nt = 0; nt < 8; nt++) {
            const int n = n0 + wn + 8 * nt + 2 * ctid;
            const int h = n >> 6, d = n & 63;
            float* base = dst + ((size_t)(b1 * HH + h) * TT + t1) * DD + d;
            *(float2*)base = make_float2(to_tf32(acc[i][nt][0]),
                                         to_tf32(acc[i][nt][1]));
            *(float2*)(base + 8 * DD) = make_float2(to_tf32(acc[i][nt][2]),
                                                    to_tf32(acc[i][nt][3]));
        }
    }
}

// ---------------------------------------------------------------------------
// fast exp2 (FMA polynomial). Clamp handles masked -1e30 inputs (-> ~2^-126).
// ---------------------------------------------------------------------------
__device__ __forceinline__ float fexp2(float t)
{
    t = fmaxf(t, -126.0f);
    float r = t + 12582912.0f;
    int   n = __float_as_int(r) - 0x4B400000;
    float x = t - (r - 12582912.0f);
    float p = 1.33335581e-3f;
    p = fmaf(p, x, 9.61812910e-3f);
    p = fmaf(p, x, 5.55041087e-2f);
    p = fmaf(p, x, 2.40226507e-1f);
    p = fmaf(p, x, 6.93147182e-1f);
    p = fmaf(p, x, 1.0f);
    return p * __int_as_float((n + 127) << 23);
}

// ---------------------------------------------------------------------------
// Kernel 2: causal flash attention, no-max softmax, scores in log2 domain.
// grid = (8, 64), 256 threads (8 warps). 256 q-rows/block, 64-key tiles,
// cp.async Q/K staging, permuted V staging, double-buffered K/Vt, 1 sync/iter.
// P fed to MMA as raw fp32 (HW truncates to tf32).
// ---------------------------------------------------------------------------
#define AP 68
#define KVBUF (64 * AP)
#define ATTN_SMEM_BYTES ((256 * AP + 4 * KVBUF) * 4)

__global__ void __launch_bounds__(256) attn_kernel()
{
    extern __shared__ float sm[];
    float* Qs = sm;                   // [256][AP]
    float* Ks = Qs + 256 * AP;        // [2][64][AP]
    float* Vt = Ks + 2 * KVBUF;       // [2][64][AP]  V^T, keys permuted

    const int t    = threadIdx.x;
    const int lane = t & 31;
    const int wid  = t >> 5;
    const int g    = lane >> 2;
    const int ctid = lane & 3;
    const int bh   = blockIdx.y;
    const int qi   = gridDim.x - 1 - blockIdx.x;   // heavy tiles first
    const int t0   = qi * 256;

    const float* Qg = g_Q + (size_t)bh * TT * DD;
    const float* Kg = g_K + (size_t)bh * TT * DD;
    const float* Vg = g_V + (size_t)bh * TT * DD;

    const int arow = (lane & 7) + ((lane >> 3) & 1) * 8;
    const int akw  = (lane >> 4) * 4;
    const int brow = (lane & 7) + (lane >> 4) * 8;
    const int bkw  = ((lane >> 3) & 1) * 4;

    const uint32_t aQ0 = smem_u32(Qs) + (((wid * 32 + arow) * AP + akw) << 2);
    const uint32_t aQ1 = aQ0 + (16 * AP << 2);
    const uint32_t bK  = smem_u32(Ks) + ((brow * AP + bkw) << 2);
    const uint32_t bV  = smem_u32(Vt) + ((brow * AP + bkw) << 2);
    const uint32_t PSTRIDE = 16 * AP * 4;
    const uint32_t BUFB    = KVBUF * 4;

    // staging index math (256 threads)
    const int qr  = t >> 4;               // 0..15
    const int c16 = t & 15;
    const uint32_t qDst = smem_u32(Qs) + qr * (AP * 4) + c16 * 16;
    const uint32_t kDst = smem_u32(Ks) + qr * (AP * 4) + c16 * 16;

    const int kq  = (t & 15) * 4;         // V: output col group base
    const int d4  = (t >> 4) * 4;         // V: d base (4 cols)
    const int vcb = kq & ~7;
    const int vo8 = kq & 7;               // 0 or 4
    const int koff = vo8 >> 2;            // 0 or 1

    // ---- prologue: Q (16 chunks/thread) + K0 (4 chunks/thread) ----
    #pragma unroll
    for (int it = 0; it < 16; it++) {
        const int r = qr + it * 16;
        CPA16(qDst + it * 16 * (AP * 4), Qg + (size_t)(t0 + r) * DD + c16 * 4);
    }
    #pragma unroll
    for (int it = 0; it < 4; it++) {
        const int r = qr + it * 16;
        CPA16(kDst + it * 16 * (AP * 4), Kg + (size_t)r * DD + c16 * 4);
    }
    CPA_COMMIT();

    float4 vreg[4];
    #pragma unroll
    for (int i = 0; i < 4; i++)
        vreg[i] = *(const float4*)&Vg[(size_t)(vcb + 2 * i + koff) * DD + d4];
    #pragma unroll
    for (int c = 0; c < 4; c++) {
        float4 w = make_float4(((const float*)&vreg[0])[c], ((const float*)&vreg[1])[c],
                               ((const float*)&vreg[2])[c], ((const float*)&vreg[3])[c]);
        *(float4*)&Vt[(d4 + c) * AP + vcb + vo8] = w;
    }
    CPA_WAIT0();
    __syncthreads();

    float o[2][8][4];
    #pragma unroll
    for (int i = 0; i < 2; i++)
        #pragma unroll
        for (int nt = 0; nt < 8; nt++)
            #pragma unroll
            for (int c = 0; c < 4; c++) o[i][nt][c] = 0.f;
    float lrw[2][2] = {{0.f, 0.f}, {0.f, 0.f}};   // per-thread partial sums

    const int wrow = t0 + wid * 32 + g;
    const int jmax = 4 * qi + 3;

    for (int j = 0; j <= jmax; j++) {
        const int cur = j & 1;
        const uint32_t bKc = bK + cur * BUFB;
        const uint32_t bVc = bV + cur * BUFB;

        // issue next tile: K via cp.async, V via LDG->regs
        if (j < jmax) {
            const int kb = (j + 1) * 64;
            const int nb = cur ^ 1;
            #pragma unroll
            for (int it = 0; it < 4; it++) {
                const int r = qr + it * 16;
                CPA16(kDst + nb * BUFB + it * 16 * (AP * 4),
                      Kg + (size_t)(kb + r) * DD + c16 * 4);
            }
            CPA_COMMIT();
            #pragma unroll
            for (int i = 0; i < 4; i++)
                vreg[i] = *(const float4*)&Vg[(size_t)(kb + vcb + 2 * i + koff) * DD + d4];
        }

        // ---- S = Q * K^T (already in log2 domain via Wq scale) ----
        float s[2][8][4];
        #pragma unroll
        for (int i = 0; i < 2; i++)
            #pragma unroll
            for (int nt = 0; nt < 8; nt++)
                #pragma unroll
                for (int c = 0; c < 4; c++) s[i][nt][c] = 0.f;

        #pragma unroll
        for (int kk = 0; kk < 8; kk++) {
            uint32_t a0[4], a1[4];
            LDSM4(a0, aQ0 + kk * 32);
            LDSM4(a1, aQ1 + kk * 32);
            #pragma unroll
            for (int p = 0; p < 4; p++) {
                uint32_t b[4];
                LDSM4(b, bKc + p * PSTRIDE + kk * 32);
                MMA_TF32(s[0][2 * p],     a0, b[0], b[1]);
                MMA_TF32(s[0][2 * p + 1], a0, b[2], b[3]);
                MMA_TF32(s[1][2 * p],     a1, b[0], b[1]);
                MMA_TF32(s[1][2 * p + 1], a1, b[2], b[3]);
            }
        }

        // causal mask
        if (j >= 4 * qi) {
            const int kb = j * 64;
            #pragma unroll
            for (int i = 0; i < 2; i++) {
                const int rlo = wrow + 16 * i, rhi = rlo + 8;
                #pragma unroll
                for (int nt = 0; nt < 8; nt++) {
                    const int cg = kb + 8 * nt + 2 * ctid;
                    if (cg     > rlo) s[i][nt][0] = -1e30f;
                    if (cg + 1 > rlo) s[i][nt][1] = -1e30f;
                    if (cg     > rhi) s[i][nt][2] = -1e30f;
                    if (cg + 1 > rhi) s[i][nt][3] = -1e30f;
                }
            }
        }

        // ---- no-max softmax: p = exp2(s); raw fp32 kept for MMA ----
        #pragma unroll
        for (int i = 0; i < 2; i++) {
            float rs0 = 0.f, rs8 = 0.f;
            #pragma unroll
            for (int nt = 0; nt < 8; nt++) {
                const float p0 = fexp2(s[i][nt][0]);
                const float p1 = fexp2(s[i][nt][1]);
                const float p2 = fexp2(s[i][nt][2]);
                const float p3 = fexp2(s[i][nt][3]);
                rs0 += p0 + p1;
                rs8 += p2 + p3;
                s[i][nt][0] = p0;
                s[i][nt][1] = p1;
                s[i][nt][2] = p2;
                s[i][nt][3] = p3;
            }
            lrw[i][0] += rs0;
            lrw[i][1] += rs8;
        }

        // ---- O += P * V : acc regs ARE the A-frag (V keys pre-permuted) ----
        #pragma unroll
        for (int kk = 0; kk < 8; kk++) {
            #pragma unroll
            for (int p = 0; p < 4; p++) {
                uint32_t b[4];
                LDSM4(b, bVc + p * PSTRIDE + kk * 32);
                MMA_TF32_ACC_A(o[0][2 * p],
                               __float_as_uint(s[0][kk][0]), __float_as_uint(s[0][kk][1]),
                               __float_as_uint(s[0][kk][2]), __float_as_uint(s[0][kk][3]),
                               b[0], b[1]);
                MMA_TF32_ACC_A(o[0][2 * p + 1],
                               __float_as_uint(s[0][kk][0]), __float_as_uint(s[0][kk][1]),
                               __float_as_uint(s[0][kk][2]), __float_as_uint(s[0][kk][3]),
                               b[2], b[3]);
                MMA_TF32_ACC_A(o[1][2 * p],
                               __float_as_uint(s[1][kk][0]), __float_as_uint(s[1][kk][1]),
                               __float_as_uint(s[1][kk][2]), __float_as_uint(s[1][kk][3]),
                               b[0], b[1]);
                MMA_TF32_ACC_A(o[1][2 * p + 1],
                               __float_as_uint(s[1][kk][0]), __float_as_uint(s[1][kk][1]),
                               __float_as_uint(s[1][kk][2]), __float_as_uint(s[1][kk][3]),
                               b[2], b[3]);
            }
        }

        // ---- publish next V tile; wait for next K tile ----
        if (j < jmax) {
            const int nb = cur ^ 1;
            float* Vtn = Vt + nb * KVBUF;
            #pragma unroll
            for (int c = 0; c < 4; c++) {
                float4 w = make_float4(((const float*)&vreg[0])[c],
                                       ((const float*)&vreg[1])[c],
                                       ((const float*)&vreg[2])[c],
                                       ((const float*)&vreg[3])[c]);
                *(float4*)&Vtn[(d4 + c) * AP + vcb + vo8] = w;
            }
            CPA_WAIT0();
        }
        __syncthreads();
    }

    // deferred l reduction (quad shfl, once)
    #pragma unroll
    for (int i = 0; i < 2; i++) {
        lrw[i][0] += __shfl_xor_sync(0xffffffffu, lrw[i][0], 1);
        lrw[i][0] += __shfl_xor_sync(0xffffffffu, lrw[i][0], 2);
        lrw[i][1] += __shfl_xor_sync(0xffffffffu, lrw[i][1], 1);
        lrw[i][1] += __shfl_xor_sync(0xffffffffu, lrw[i][1], 2);
    }

    // epilogue: normalize + round + merge heads into g_Y [B,T,C]
    const int b1 = bh >> 4, h = bh & 15;
    #pragma unroll
    for (int i = 0; i < 2; i++) {
        const float li0 = 1.0f / lrw[i][0], li8 = 1.0f / lrw[i][1];
        const int r0 = wrow + 16 * i;
        float* y0 = g_Y + (size_t)(b1 * TT + r0) * CC + h * 64;
        float* y8 = y0 + (size_t)8 * CC;
        #pragma unroll
        for (int nt = 0; nt < 8; nt++) {
            *(float2*)&y0[8 * nt + 2 * ctid] =
                make_float2(to_tf32(o[i][nt][0] * li0), to_tf32(o[i][nt][1] * li0));
            *(float2*)&y8[8 * nt + 2 * ctid] =
                make_float2(to_tf32(o[i][nt][2] * li8), to_tf32(o[i][nt][3] * li8));
        }
    }
}

// ---------------------------------------------------------------------------
// Kernel 3: output projection. grid = (8, 64), 128 threads, dyn smem.
// ---------------------------------------------------------------------------
__global__ void __launch_bounds__(128) outproj_kernel(const float* __restrict__ bo,
                                                      float* __restrict__ out)
{
    extern __shared__ float gsm[];
    const int m0 = blockIdx.y * 128;
    const int n0 = blockIdx.x * 128;

    float acc[4][8][4];
    gemm_tf32(gsm, g_Y, g_Wo, m0, n0, acc);

    const int lane = threadIdx.x & 31, wid = threadIdx.x >> 5;
    const int g = lane >> 2, ctid = lane & 3;
    const int wm = (wid & 1) * 64, wn = (wid >> 1) * 64;

    #pragma unroll
    for (int i = 0; i < 4; i++) {
        const int m = m0 + wm + 16 * i + g;
        #pragma unroll
        for (int nt = 0; nt < 8; nt++) {
            const int n = n0 + wn + 8 * nt + 2 * ctid;
            const float2 bias = *(const float2*)&bo[n];
            float* base = out + (size_t)m * CC + n;
            *(float2*)base = make_float2(acc[i][nt][0] + bias.x, acc[i][nt][1] + bias.y);
            *(float2*)(base + (size_t)8 * CC) =
                make_float2(acc[i][nt][2] + bias.x, acc[i][nt][3] + bias.y);
        }
    }
}

// ---------------------------------------------------------------------------
// Launch
// ---------------------------------------------------------------------------
extern "C" void kernel_launch(void* const* d_in, const int* in_sizes, int n_in,
                              void* d_out, int out_size)
{
    const float* x  = (const float*)d_in[0];
    const float* Wq = (const float*)d_in[1];
    const float* Wk = (const float*)d_in[2];
    const float* Wv = (const float*)d_in[3];
    const float* Wo = (const float*)d_in[4];
    const float* bo = (const float*)d_in[5];
    float* out = (float*)d_out;

    cudaFuncSetAttribute(attn_kernel, cudaFuncAttributeMaxDynamicSharedMemorySize,
                         ATTN_SMEM_BYTES);
    cudaFuncSetAttribute(qkv_kernel, cudaFuncAttributeMaxDynamicSharedMemorySize,
                         GEMM_SMEM_BYTES);
    cudaFuncSetAttribute(outproj_kernel, cudaFuncAttributeMaxDynamicSharedMemorySize,
                         GEMM_SMEM_BYTES);

    const int nX4 = BB * TT * CC / 4;
    const int nW4 = CC * CC / 4;
    round_x_kernel<<<(nX4 + 255) / 256, 256>>>(x, nX4);
    round_w_kernel<<<dim3((nW4 + 255) / 256, 4), 256>>>(Wq, Wk, Wv, Wo, nW4);

    qkv_kernel<<<dim3(8, 64, 3), 128, GEMM_SMEM_BYTES>>>();
    attn_kernel<<<dim3(8, 64), 256, ATTN_SMEM_BYTES>>>();
    outproj_kernel<<<dim3(8, 64), 128, GEMM_SMEM_BYTES>>>(bo, out);
}

// round 17
// speedup vs baseline: 1.0220x; 1.0220x over previous
#include <cuda_runtime.h>
#include <cstdint>

// ---------------------------------------------------------------------------
// SABlock: causal MHA block. B=4, T=2048, C=1024, H=16, D=64.
// Round 17: composition of measured bests. GEMM = round-14 2-stage static
// (3-stage regressed). Attention = round-16 (log2-domain scores via Wq fold,
// raw-fp32 P into MMA, no-max softmax, deferred l-reduction).
// ---------------------------------------------------------------------------

#define BB 4
#define TT 2048
#define CC 1024
#define HH 16
#define DD 64

__device__ __align__(16) float g_X[BB * TT * CC];
__device__ __align__(16) float g_Wq[CC * CC];
__device__ __align__(16) float g_Wk[CC * CC];
__device__ __align__(16) float g_Wv[CC * CC];
__device__ __align__(16) float g_Wo[CC * CC];
__device__ __align__(16) float g_Q[BB * HH * TT * DD];
__device__ __align__(16) float g_K[BB * HH * TT * DD];
__device__ __align__(16) float g_V[BB * HH * TT * DD];
__device__ __align__(16) float g_Y[BB * TT * CC];

__device__ __forceinline__ float to_tf32(float x) {
    uint32_t u;
    asm("cvt.rna.tf32.f32 %0, %1;" : "=r"(u) : "f"(x));
    return __uint_as_float(u);
}
__device__ __forceinline__ uint32_t smem_u32(const void* p) {
    return (uint32_t)__cvta_generic_to_shared(p);
}

#define CPA16(dst, src)                                                       \
    asm volatile("cp.async.cg.shared.global [%0], [%1], 16;"                  \
                 :: "r"(dst), "l"(src) : "memory")
#define CPA_COMMIT() asm volatile("cp.async.commit_group;" ::: "memory")
#define CPA_WAIT0()  asm volatile("cp.async.wait_group 0;" ::: "memory")

#define LDSM4(r, addr)                                                        \
    asm volatile("ldmatrix.sync.aligned.m8n8.x4.shared.b16 {%0,%1,%2,%3}, [%4];" \
                 : "=r"((r)[0]), "=r"((r)[1]), "=r"((r)[2]), "=r"((r)[3])     \
                 : "r"(addr))

#define MMA_TF32(c, a, b0_, b1_)                                              \
    asm volatile("mma.sync.aligned.m16n8k8.row.col.f32.tf32.tf32.f32 "        \
                 "{%0,%1,%2,%3},{%4,%5,%6,%7},{%8,%9},{%0,%1,%2,%3};"         \
                 : "+f"((c)[0]), "+f"((c)[1]), "+f"((c)[2]), "+f"((c)[3])     \
                 : "r"((a)[0]), "r"((a)[1]), "r"((a)[2]), "r"((a)[3]),        \
                   "r"(b0_), "r"(b1_))

// A-frag direct from S accumulator: register order (c0, c2, c1, c3).
#define MMA_TF32_ACC_A(c, s0_, s1_, s2_, s3_, b0_, b1_)                       \
    asm volatile("mma.sync.aligned.m16n8k8.row.col.f32.tf32.tf32.f32 "        \
                 "{%0,%1,%2,%3},{%4,%5,%6,%7},{%8,%9},{%0,%1,%2,%3};"         \
                 : "+f"((c)[0]), "+f"((c)[1]), "+f"((c)[2]), "+f"((c)[3])     \
                 : "r"(s0_), "r"(s2_), "r"(s1_), "r"(s3_),                    \
                   "r"(b0_), "r"(b1_))

// ---------------------------------------------------------------------------
// Kernel 0a: RNA-round x -> g_X. Kernel 0b: round weights.
// Wq pre-scaled by 0.125*log2(e) -> QK^T lands directly in log2 domain.
// ---------------------------------------------------------------------------
__global__ void round_x_kernel(const float* __restrict__ src, int n4)
{
    int i = blockIdx.x * blockDim.x + threadIdx.x;
    if (i < n4) {
        float4 v = ((const float4*)src)[i];
        ((float4*)g_X)[i] = make_float4(to_tf32(v.x), to_tf32(v.y),
                                        to_tf32(v.z), to_tf32(v.w));
    }
}

__global__ void round_w_kernel(const float* __restrict__ wq,
                               const float* __restrict__ wk,
                               const float* __restrict__ wv,
                               const float* __restrict__ wo, int n4)
{
    const int y = blockIdx.y;
    const float* src = (y == 0) ? wq : (y == 1) ? wk : (y == 2) ? wv : wo;
    float* dst = (y == 0) ? g_Wq : (y == 1) ? g_Wk : (y == 2) ? g_Wv : g_Wo;
    const float sc = (y == 0) ? 0.125f * 1.4426950408889634f : 1.0f;
    int i = blockIdx.x * blockDim.x + threadIdx.x;
    if (i < n4) {
        float4 v = ((const float4*)src)[i];
        ((float4*)dst)[i] = make_float4(to_tf32(v.x * sc), to_tf32(v.y * sc),
                                        to_tf32(v.z * sc), to_tf32(v.w * sc));
    }
}

// ---------------------------------------------------------------------------
// tf32 GEMM core (round-14 proven): 2-stage cp.async, static smem.
// 128x128 block tile, 4 warps 64x64, K-step 16, 1 sync/kt.
// ---------------------------------------------------------------------------
__device__ __forceinline__ void gemm_tf32(const float* __restrict__ A,
                                          const float* __restrict__ W,
                                          int m0, int n0, float acc[4][8][4])
{
    __shared__ float As[2][128][20];
    __shared__ float Bs[2][128][20];

    const int t    = threadIdx.x;
    const int lane = t & 31;
    const int wid  = t >> 5;
    const int wm   = (wid & 1) * 64;
    const int wn   = (wid >> 1) * 64;

    const int lr = t >> 2;                  // 0..31
    const int lc = (t & 3) * 4;             // 0,4,8,12
    const float* Ap = A + (size_t)(m0 + lr) * CC + lc;
    const float* Bp = W + (size_t)(n0 + lr) * CC + lc;

    const uint32_t aSt = smem_u32(&As[0][0][0]) + lr * 80 + lc * 4;
    const uint32_t bSt = smem_u32(&Bs[0][0][0]) + lr * 80 + lc * 4;

    const int arow = (lane & 7) + ((lane >> 3) & 1) * 8;
    const int akw  = (lane >> 4) * 4;
    const int brow = (lane & 7) + (lane >> 4) * 8;
    const int bkw  = ((lane >> 3) & 1) * 4;

    const uint32_t aBase = smem_u32(&As[0][0][0]) + (((wm + arow) * 20 + akw) << 2);
    const uint32_t bBase = smem_u32(&Bs[0][0][0]) + (((wn + brow) * 20 + bkw) << 2);
    const uint32_t BUF   = 10240;           // 128*20*4

    #pragma unroll
    for (int i = 0; i < 4; i++)
        #pragma unroll
        for (int nt = 0; nt < 8; nt++)
            #pragma unroll
            for (int c = 0; c < 4; c++) acc[i][nt][c] = 0.f;

    // prologue: stage kt=0 into buffer 0
    #pragma unroll
    for (int i = 0; i < 4; i++) {
        CPA16(aSt + i * 2560, Ap + (size_t)(32 * i) * CC);
        CPA16(bSt + i * 2560, Bp + (size_t)(32 * i) * CC);
    }
    CPA_COMMIT();

    for (int kt = 0; kt < CC / 16; kt++) {
        const int cur = kt & 1;
        CPA_WAIT0();
        __syncthreads();

        if (kt + 1 < CC / 16) {
            const int nb = cur ^ 1;
            const float* Ap2 = Ap + (kt + 1) * 16;
            const float* Bp2 = Bp + (kt + 1) * 16;
            #pragma unroll
            for (int i = 0; i < 4; i++) {
                CPA16(aSt + nb * BUF + i * 2560, Ap2 + (size_t)(32 * i) * CC);
                CPA16(bSt + nb * BUF + i * 2560, Bp2 + (size_t)(32 * i) * CC);
            }
            CPA_COMMIT();
        }

        const uint32_t aB = aBase + cur * BUF;
        const uint32_t bB = bBase + cur * BUF;
        #pragma unroll
        for (int kk = 0; kk < 2; kk++) {
            uint32_t a[4][4];
            #pragma unroll
            for (int i = 0; i < 4; i++)
                LDSM4(a[i], aB + i * 1280 + kk * 32);
            #pragma unroll
            for (int p = 0; p < 4; p++) {
                uint32_t b[4];
                LDSM4(b, bB + p * 1280 + kk * 32);
                #pragma unroll
                for (int i = 0; i < 4; i++) {
                    MMA_TF32(acc[i][2 * p],     a[i], b[0], b[1]);
                    MMA_TF32(acc[i][2 * p + 1], a[i], b[2], b[3]);
                }
            }
        }
    }
}

// ---------------------------------------------------------------------------
// Kernel 1: fused QKV projection. grid = (8, 64, 3), 128 threads.
// ---------------------------------------------------------------------------
__global__ void __launch_bounds__(128) qkv_kernel()
{
    const int z = blockIdx.z;
    const float* W = (z == 0) ? g_Wq : (z == 1) ? g_Wk : g_Wv;
    float* dst     = (z == 0) ? g_Q : (z == 1) ? g_K : g_V;

    const int m0 = blockIdx.y * 128;
    const int n0 = blockIdx.x * 128;

    float acc[4][8][4];
    gemm_tf32(g_X, W, m0, n0, acc);

    const int lane = threadIdx.x & 31, wid = threadIdx.x >> 5;
    const int g = lane >> 2, ctid = lane & 3;
    const int wm = (wid & 1) * 64, wn = (wid >> 1) * 64;

    #pragma unroll
    for (int i = 0; i < 4; i++) {
        const int m = m0 + wm + 16 * i + g;
        const int b1 = m >> 11;
        const int t1 = m & (TT - 1);
        #pragma unroll
        for (int nt = 0; nt < 8; nt++) {
            const int n = n0 + wn + 8 * nt + 2 * ctid;
            const int h = n >> 6, d = n & 63;
            float* base = dst + ((size_t)(b1 * HH + h) * TT + t1) * DD + d;
            *(float2*)base = make_float2(to_tf32(acc[i][nt][0]),
                                         to_tf32(acc[i][nt][1]));
            *(float2*)(base + 8 * DD) = make_float2(to_tf32(acc[i][nt][2]),
                                                    to_tf32(acc[i][nt][3]));
        }
    }
}

// ---------------------------------------------------------------------------
// fast exp2 (FMA polynomial). Clamp handles masked -1e30 inputs (-> ~2^-126).
// ---------------------------------------------------------------------------
__device__ __forceinline__ float fexp2(float t)
{
    t = fmaxf(t, -126.0f);
    float r = t + 12582912.0f;
    int   n = __float_as_int(r) - 0x4B400000;
    float x = t - (r - 12582912.0f);
    float p = 1.33335581e-3f;
    p = fmaf(p, x, 9.61812910e-3f);
    p = fmaf(p, x, 5.55041087e-2f);
    p = fmaf(p, x, 2.40226507e-1f);
    p = fmaf(p, x, 6.93147182e-1f);
    p = fmaf(p, x, 1.0f);
    return p * __int_as_float((n + 127) << 23);
}

// ---------------------------------------------------------------------------
// Kernel 2: causal flash attention, no-max softmax, scores in log2 domain.
// grid = (8, 64), 256 threads (8 warps). 256 q-rows/block, 64-key tiles,
// cp.async Q/K staging, permuted V staging, double-buffered K/Vt, 1 sync/iter.
// P fed to MMA as raw fp32 (HW truncates to tf32).
// ---------------------------------------------------------------------------
#define AP 68
#define KVBUF (64 * AP)
#define ATTN_SMEM_BYTES ((256 * AP + 4 * KVBUF) * 4)

__global__ void __launch_bounds__(256) attn_kernel()
{
    extern __shared__ float sm[];
    float* Qs = sm;                   // [256][AP]
    float* Ks = Qs + 256 * AP;        // [2][64][AP]
    float* Vt = Ks + 2 * KVBUF;       // [2][64][AP]  V^T, keys permuted

    const int t    = threadIdx.x;
    const int lane = t & 31;
    const int wid  = t >> 5;
    const int g    = lane >> 2;
    const int ctid = lane & 3;
    const int bh   = blockIdx.y;
    const int qi   = gridDim.x - 1 - blockIdx.x;   // heavy tiles first
    const int t0   = qi * 256;

    const float* Qg = g_Q + (size_t)bh * TT * DD;
    const float* Kg = g_K + (size_t)bh * TT * DD;
    const float* Vg = g_V + (size_t)bh * TT * DD;

    const int arow = (lane & 7) + ((lane >> 3) & 1) * 8;
    const int akw  = (lane >> 4) * 4;
    const int brow = (lane & 7) + (lane >> 4) * 8;
    const int bkw  = ((lane >> 3) & 1) * 4;

    const uint32_t aQ0 = smem_u32(Qs) + (((wid * 32 + arow) * AP + akw) << 2);
    const uint32_t aQ1 = aQ0 + (16 * AP << 2);
    const uint32_t bK  = smem_u32(Ks) + ((brow * AP + bkw) << 2);
    const uint32_t bV  = smem_u32(Vt) + ((brow * AP + bkw) << 2);
    const uint32_t PSTRIDE = 16 * AP * 4;
    const uint32_t BUFB    = KVBUF * 4;

    // staging index math (256 threads)
    const int qr  = t >> 4;               // 0..15
    const int c16 = t & 15;
    const uint32_t qDst = smem_u32(Qs) + qr * (AP * 4) + c16 * 16;
    const uint32_t kDst = smem_u32(Ks) + qr * (AP * 4) + c16 * 16;

    const int kq  = (t & 15) * 4;         // V: output col group base
    const int d4  = (t >> 4) * 4;         // V: d base (4 cols)
    const int vcb = kq & ~7;
    const int vo8 = kq & 7;               // 0 or 4
    const int koff = vo8 >> 2;            // 0 or 1

    // ---- prologue: Q (16 chunks/thread) + K0 (4 chunks/thread) ----
    #pragma unroll
    for (int it = 0; it < 16; it++) {
        const int r = qr + it * 16;
        CPA16(qDst + it * 16 * (AP * 4), Qg + (size_t)(t0 + r) * DD + c16 * 4);
    }
    #pragma unroll
    for (int it = 0; it < 4; it++) {
        const int r = qr + it * 16;
        CPA16(kDst + it * 16 * (AP * 4), Kg + (size_t)r * DD + c16 * 4);
    }
    CPA_COMMIT();

    float4 vreg[4];
    #pragma unroll
    for (int i = 0; i < 4; i++)
        vreg[i] = *(const float4*)&Vg[(size_t)(vcb + 2 * i + koff) * DD + d4];
    #pragma unroll
    for (int c = 0; c < 4; c++) {
        float4 w = make_float4(((const float*)&vreg[0])[c], ((const float*)&vreg[1])[c],
                               ((const float*)&vreg[2])[c], ((const float*)&vreg[3])[c]);
        *(float4*)&Vt[(d4 + c) * AP + vcb + vo8] = w;
    }
    CPA_WAIT0();
    __syncthreads();

    float o[2][8][4];
    #pragma unroll
    for (int i = 0; i < 2; i++)
        #pragma unroll
        for (int nt = 0; nt < 8; nt++)
            #pragma unroll
            for (int c = 0; c < 4; c++) o[i][nt][c] = 0.f;
    float lrw[2][2] = {{0.f, 0.f}, {0.f, 0.f}};   // per-thread partial sums

    const int wrow = t0 + wid * 32 + g;
    const int jmax = 4 * qi + 3;

    for (int j = 0; j <= jmax; j++) {
        const int cur = j & 1;
        const uint32_t bKc = bK + cur * BUFB;
        const uint32_t bVc = bV + cur * BUFB;

        // issue next tile: K via cp.async, V via LDG->regs
        if (j < jmax) {
            const int kb = (j + 1) * 64;
            const int nb = cur ^ 1;
            #pragma unroll
            for (int it = 0; it < 4; it++) {
                const int r = qr + it * 16;
                CPA16(kDst + nb * BUFB + it * 16 * (AP * 4),
                      Kg + (size_t)(kb + r) * DD + c16 * 4);
            }
            CPA_COMMIT();
            #pragma unroll
            for (int i = 0; i < 4; i++)
                vreg[i] = *(const float4*)&Vg[(size_t)(kb + vcb + 2 * i + koff) * DD + d4];
        }

        // ---- S = Q * K^T (already in log2 domain via Wq scale) ----
        float s[2][8][4];
        #pragma unroll
        for (int i = 0; i < 2; i++)
            #pragma unroll
            for (int nt = 0; nt < 8; nt++)
                #pragma unroll
                for (int c = 0; c < 4; c++) s[i][nt][c] = 0.f;

        #pragma unroll
        for (int kk = 0; kk < 8; kk++) {
            uint32_t a0[4], a1[4];
            LDSM4(a0, aQ0 + kk * 32);
            LDSM4(a1, aQ1 + kk * 32);
            #pragma unroll
            for (int p = 0; p < 4; p++) {
                uint32_t b[4];
                LDSM4(b, bKc + p * PSTRIDE + kk * 32);
                MMA_TF32(s[0][2 * p],     a0, b[0], b[1]);
                MMA_TF32(s[0][2 * p + 1], a0, b[2], b[3]);
                MMA_TF32(s[1][2 * p],     a1, b[0], b[1]);
                MMA_TF32(s[1][2 * p + 1], a1, b[2], b[3]);
            }
        }

        // causal mask
        if (j >= 4 * qi) {
            const int kb = j * 64;
            #pragma unroll
            for (int i = 0; i < 2; i++) {
                const int rlo = wrow + 16 * i, rhi = rlo + 8;
                #pragma unroll
                for (int nt = 0; nt < 8; nt++) {
                    const int cg = kb + 8 * nt + 2 * ctid;
                    if (cg     > rlo) s[i][nt][0] = -1e30f;
                    if (cg + 1 > rlo) s[i][nt][1] = -1e30f;
                    if (cg     > rhi) s[i][nt][2] = -1e30f;
                    if (cg + 1 > rhi) s[i][nt][3] = -1e30f;
                }
            }
        }

        // ---- no-max softmax: p = exp2(s); raw fp32 kept for MMA ----
        #pragma unroll
        for (int i = 0; i < 2; i++) {
            float rs0 = 0.f, rs8 = 0.f;
            #pragma unroll
            for (int nt = 0; nt < 8; nt++) {
                const float p0 = fexp2(s[i][nt][0]);
                const float p1 = fexp2(s[i][nt][1]);
                const float p2 = fexp2(s[i][nt][2]);
                const float p3 = fexp2(s[i][nt][3]);
                rs0 += p0 + p1;
                rs8 += p2 + p3;
                s[i][nt][0] = p0;
                s[i][nt][1] = p1;
                s[i][nt][2] = p2;
                s[i][nt][3] = p3;
            }
            lrw[i][0] += rs0;
            lrw[i][1] += rs8;
        }

        // ---- O += P * V : acc regs ARE the A-frag (V keys pre-permuted) ----
        #pragma unroll
        for (int kk = 0; kk < 8; kk++) {
            #pragma unroll
            for (int p = 0; p < 4; p++) {
                uint32_t b[4];
                LDSM4(b, bVc + p * PSTRIDE + kk * 32);
                MMA_TF32_ACC_A(o[0][2 * p],
                               __float_as_uint(s[0][kk][0]), __float_as_uint(s[0][kk][1]),
                               __float_as_uint(s[0][kk][2]), __float_as_uint(s[0][kk][3]),
                               b[0], b[1]);
                MMA_TF32_ACC_A(o[0][2 * p + 1],
                               __float_as_uint(s[0][kk][0]), __float_as_uint(s[0][kk][1]),
                               __float_as_uint(s[0][kk][2]), __float_as_uint(s[0][kk][3]),
                               b[2], b[3]);
                MMA_TF32_ACC_A(o[1][2 * p],
                               __float_as_uint(s[1][kk][0]), __float_as_uint(s[1][kk][1]),
                               __float_as_uint(s[1][kk][2]), __float_as_uint(s[1][kk][3]),
                               b[0], b[1]);
                MMA_TF32_ACC_A(o[1][2 * p + 1],
                               __float_as_uint(s[1][kk][0]), __float_as_uint(s[1][kk][1]),
                               __float_as_uint(s[1][kk][2]), __float_as_uint(s[1][kk][3]),
                               b[2], b[3]);
            }
        }

        // ---- publish next V tile; wait for next K tile ----
        if (j < jmax) {
            const int nb = cur ^ 1;
            float* Vtn = Vt + nb * KVBUF;
            #pragma unroll
            for (int c = 0; c < 4; c++) {
                float4 w = make_float4(((const float*)&vreg[0])[c],
                                       ((const float*)&vreg[1])[c],
                                       ((const float*)&vreg[2])[c],
                                       ((const float*)&vreg[3])[c]);
                *(float4*)&Vtn[(d4 + c) * AP + vcb + vo8] = w;
            }
            CPA_WAIT0();
        }
        __syncthreads();
    }

    // deferred l reduction (quad shfl, once)
    #pragma unroll
    for (int i = 0; i < 2; i++) {
        lrw[i][0] += __shfl_xor_sync(0xffffffffu, lrw[i][0], 1);
        lrw[i][0] += __shfl_xor_sync(0xffffffffu, lrw[i][0], 2);
        lrw[i][1] += __shfl_xor_sync(0xffffffffu, lrw[i][1], 1);
        lrw[i][1] += __shfl_xor_sync(0xffffffffu, lrw[i][1], 2);
    }

    // epilogue: normalize + round + merge heads into g_Y [B,T,C]
    const int b1 = bh >> 4, h = bh & 15;
    #pragma unroll
    for (int i = 0; i < 2; i++) {
        const float li0 = 1.0f / lrw[i][0], li8 = 1.0f / lrw[i][1];
        const int r0 = wrow + 16 * i;
        float* y0 = g_Y + (size_t)(b1 * TT + r0) * CC + h * 64;
        float* y8 = y0 + (size_t)8 * CC;
        #pragma unroll
        for (int nt = 0; nt < 8; nt++) {
            *(float2*)&y0[8 * nt + 2 * ctid] =
                make_float2(to_tf32(o[i][nt][0] * li0), to_tf32(o[i][nt][1] * li0));
            *(float2*)&y8[8 * nt + 2 * ctid] =
                make_float2(to_tf32(o[i][nt][2] * li8), to_tf32(o[i][nt][3] * li8));
        }
    }
}

// ---------------------------------------------------------------------------
// Kernel 3: output projection  out = Y @ Wo^T + bo.  grid = (8, 64), 128 thr.
// ---------------------------------------------------------------------------
__global__ void __launch_bounds__(128) outproj_kernel(const float* __restrict__ bo,
                                                      float* __restrict__ out)
{
    const int m0 = blockIdx.y * 128;
    const int n0 = blockIdx.x * 128;

    float acc[4][8][4];
    gemm_tf32(g_Y, g_Wo, m0, n0, acc);

    const int lane = threadIdx.x & 31, wid = threadIdx.x >> 5;
    const int g = lane >> 2, ctid = lane & 3;
    const int wm = (wid & 1) * 64, wn = (wid >> 1) * 64;

    #pragma unroll
    for (int i = 0; i < 4; i++) {
        const int m = m0 + wm + 16 * i + g;
        #pragma unroll
        for (int nt = 0; nt < 8; nt++) {
            const int n = n0 + wn + 8 * nt + 2 * ctid;
            const float2 bias = *(const float2*)&bo[n];
            float* base = out + (size_t)m * CC + n;
            *(float2*)base = make_float2(acc[i][nt][0] + bias.x, acc[i][nt][1] + bias.y);
            *(float2*)(base + (size_t)8 * CC) =
                make_float2(acc[i][nt][2] + bias.x, acc[i][nt][3] + bias.y);
        }
    }
}

// ---------------------------------------------------------------------------
// Launch
// ---------------------------------------------------------------------------
extern "C" void kernel_launch(void* const* d_in, const int* in_sizes, int n_in,
                              void* d_out, int out_size)
{
    const float* x  = (const float*)d_in[0];
    const float* Wq = (const float*)d_in[1];
    const float* Wk = (const float*)d_in[2];
    const float* Wv = (const float*)d_in[3];
    const float* Wo = (const float*)d_in[4];
    const float* bo = (const float*)d_in[5];
    float* out = (float*)d_out;

    cudaFuncSetAttribute(attn_kernel, cudaFuncAttributeMaxDynamicSharedMemorySize,
                         ATTN_SMEM_BYTES);

    const int nX4 = BB * TT * CC / 4;
    const int nW4 = CC * CC / 4;
    round_x_kernel<<<(nX4 + 255) / 256, 256>>>(x, nX4);
    round_w_kernel<<<dim3((nW4 + 255) / 256, 4), 256>>>(Wq, Wk, Wv, Wo, nW4);

    qkv_kernel<<<dim3(8, 64, 3), 128>>>();
    attn_kernel<<<dim3(8, 64), 256, ATTN_SMEM_BYTES>>>();
    outproj_kernel<<<dim3(8, 64), 128>>>(bo, out);
}